// round 3
// baseline (speedup 1.0000x reference)
#include <cuda_runtime.h>
#include <stdint.h>

// Problem constants
#define BB 64
#define CC 256
#define HH 56
#define WW 56
#define HM 50
#define WM 50
#define NPLANES (BB * CC)              // 16384
#define PLANE_IN (HM * WM)             // 2500
#define PLANE_OUT (HH * WW)            // 3136
#define NTOT ((long long)NPLANES * PLANE_OUT)   // 51,380,224
#define NMASK (NPLANES * PLANE_IN)     // 40,960,000

// Scratch: dilated block mask, 1 bit per output pixel, one uint64 per row.
__device__ unsigned long long g_bits[NPLANES * HH];   // ~7.34 MB (L2-resident)
__device__ unsigned long long g_count;                // blocked-pixel count
__device__ float g_scale;

__global__ void init_kernel() { g_count = 0ull; }

__global__ void finalize_kernel() {
    double n = (double)NTOT;
    g_scale = (float)(n / (n - (double)g_count));
}

// One CTA per (b,c) plane. Builds seed-row bitmasks, dilates 7x7, stores
// 56 row bitmasks, and accumulates blocked-pixel count.
__global__ __launch_bounds__(256) void mask_kernel(
    const float* __restrict__ mu, float gamma) {
    __shared__ unsigned long long rows[HM];
    __shared__ unsigned long long wsum[2];

    const int plane = blockIdx.x;
    const int t = threadIdx.x;

    if (t < HM) rows[t] = 0ull;
    __syncthreads();

    // Coalesced float4 read of the 2500-float plane (2500 = 625 * 4,
    // plane base is 16B-aligned).
    const float4* p = reinterpret_cast<const float4*>(mu + (size_t)plane * PLANE_IN);
    for (int i = t; i < PLANE_IN / 4; i += 256) {
        float4 v = p[i];
        int base = i * 4;
        float vals[4] = {v.x, v.y, v.z, v.w};
        #pragma unroll
        for (int j = 0; j < 4; j++) {
            if (vals[j] < gamma) {                 // rare (~0.26%)
                int idx = base + j;
                int r = idx / WM;
                int c = idx - r * WM;
                atomicOr(&rows[r], 1ull << c);
            }
        }
    }
    __syncthreads();

    // Per output row h: vertical OR over rows [h-6, h] ∩ [0, 50), then
    // horizontal 7-wide shift-OR dilation, clip to 56 bits.
    unsigned long long cnt = 0ull;
    if (t < HH) {
        unsigned long long v = 0ull;
        int lo = t - 6; if (lo < 0) lo = 0;
        int hi = t;     if (hi > HM - 1) hi = HM - 1;
        #pragma unroll 7
        for (int r = lo; r <= hi; r++) v |= rows[r];
        // window-7 dilation: {0,1} -> {0..3} -> {0..5} -> +{6}
        unsigned long long a = v | (v << 1);
        unsigned long long b = a | (a << 2);
        unsigned long long c6 = b | (b << 2);
        unsigned long long h = (c6 | (v << 6)) & ((1ull << HH) - 1ull);
        g_bits[plane * HH + t] = h;
        cnt = (unsigned long long)__popcll(h);
    }

    // Reduce cnt across the block (only warps 0,1 hold nonzero).
    #pragma unroll
    for (int o = 16; o > 0; o >>= 1)
        cnt += __shfl_down_sync(0xffffffffu, cnt, o);
    if ((t & 31) == 0 && (t >> 5) < 2) wsum[t >> 5] = cnt;
    __syncthreads();
    if (t == 0) atomicAdd(&g_count, wsum[0] + wsum[1]);
}

// float4 over x: 56 % 4 == 0 so a float4 never straddles a row.
__global__ __launch_bounds__(256) void apply_kernel(
    const float* __restrict__ x, float* __restrict__ out, int n4) {
    int i = blockIdx.x * blockDim.x + threadIdx.x;
    if (i >= n4) return;
    float4 v = reinterpret_cast<const float4*>(x)[i];
    const float s = g_scale;
    int e = i * 4;                 // element index < 2^31
    int r = e / WW;
    int c = e - r * WW;
    unsigned long long bits = g_bits[r] >> c;
    v.x = (bits & 1ull)        ? 0.0f : v.x * s;
    v.y = ((bits >> 1) & 1ull) ? 0.0f : v.y * s;
    v.z = ((bits >> 2) & 1ull) ? 0.0f : v.z * s;
    v.w = ((bits >> 3) & 1ull) ? 0.0f : v.w * s;
    reinterpret_cast<float4*>(out)[i] = v;
}

extern "C" void kernel_launch(void* const* d_in, const int* in_sizes, int n_in,
                              void* d_out, int out_size) {
    // Inputs per metadata order: x (51,380,224 f32), mask_u (40,960,000 f32).
    const float* x  = (const float*)d_in[0];
    const float* mu = (const float*)d_in[1];
    if (in_sizes[0] == NMASK) {    // defensive: swap if order differs
        x  = (const float*)d_in[1];
        mu = (const float*)d_in[0];
    }
    float* out = (float*)d_out;

    // gamma = DROP_PROB / bs^2 * feat^2 / (feat - bs + 1)^2, as float32
    // (reference compares f32 < f32(gamma)).
    const double gamma_d = 0.1 / 49.0 * (56.0 * 56.0) / (50.0 * 50.0);
    const float gamma = (float)gamma_d;

    init_kernel<<<1, 1>>>();
    mask_kernel<<<NPLANES, 256>>>(mu, gamma);
    finalize_kernel<<<1, 1>>>();
    const int n4 = (int)(NTOT / 4);
    apply_kernel<<<(n4 + 255) / 256, 256>>>(x, out, n4);
}

// round 4
// speedup vs baseline: 1.0858x; 1.0858x over previous
#include <cuda_runtime.h>
#include <stdint.h>

// Problem constants
#define BB 64
#define CC 256
#define HH 56
#define WW 56
#define HM 50
#define WM 50
#define NPLANES (BB * CC)                 // 16384
#define PLANE_IN (HM * WM)                // 2500
#define PLANE_OUT (HH * WW)               // 3136
#define NTOT ((long long)NPLANES * PLANE_OUT)   // 51,380,224
#define NMASK (NPLANES * PLANE_IN)        // 40,960,000

#define PPC 8                             // planes per mask CTA
#define MASK_GRID (NPLANES / PPC)         // 2048

// Scratch: dilated block mask, 1 bit per output pixel, one uint64 per row.
__device__ unsigned long long g_bits[NPLANES * HH];   // ~7.34 MB (L2-resident)
__device__ unsigned long long g_count = 0ull;         // blocked-pixel count
__device__ unsigned int       g_arrive = 0u;          // CTA arrival ticket
__device__ float              g_scale;

// One CTA per 8 (b,c) planes. Builds seed-row bitmasks, dilates 7x7,
// stores 8*56 row bitmasks, accumulates blocked count. The LAST CTA to
// finish computes g_scale and resets counters for the next graph replay.
__global__ __launch_bounds__(256) void mask_kernel(
    const float* __restrict__ mu, float gamma) {
    __shared__ unsigned long long rows[PPC * HM];     // 400 * 8B = 3.2 KB
    __shared__ unsigned long long wsum[8];

    const int t = threadIdx.x;
    const int base_plane = blockIdx.x * PPC;

    #pragma unroll
    for (int i = t; i < PPC * HM; i += 256) rows[i] = 0ull;
    __syncthreads();

    // 8 contiguous planes = 20000 floats = 5000 float4 (each float4 is
    // within one plane since 2500 % 4 == 0). Streaming loads; ~20/thread.
    const float4* p = reinterpret_cast<const float4*>(
        mu + (size_t)base_plane * PLANE_IN);
    const int n4 = PPC * PLANE_IN / 4;                // 5000
    #pragma unroll 4
    for (int i = t; i < n4; i += 256) {
        float4 v = __ldcs(&p[i]);
        // Rare path (~0.26% of elements): compute indices only when hit.
        if (v.x < gamma || v.y < gamma || v.z < gamma || v.w < gamma) {
            float vals[4] = {v.x, v.y, v.z, v.w};
            #pragma unroll
            for (int j = 0; j < 4; j++) {
                if (vals[j] < gamma) {
                    int idx = i * 4 + j;
                    int pl = idx / PLANE_IN;
                    int w  = idx - pl * PLANE_IN;
                    int r  = w / WM;
                    int c  = w - r * WM;
                    atomicOr(&rows[pl * HM + r], 1ull << c);
                }
            }
        }
    }
    __syncthreads();

    // 8*56 = 448 output rows over 256 threads (2 passes).
    unsigned long long cnt = 0ull;
    for (int o = t; o < PPC * HH; o += 256) {
        int pl = o / HH;
        int h  = o - pl * HH;
        unsigned long long v = 0ull;
        int lo = h - 6; if (lo < 0) lo = 0;
        int hi = h;     if (hi > HM - 1) hi = HM - 1;
        #pragma unroll 7
        for (int r = lo; r <= hi; r++) v |= rows[pl * HM + r];
        // 7-wide horizontal dilation via shift-OR, clip to 56 bits.
        unsigned long long a  = v | (v << 1);
        unsigned long long b  = a | (a << 2);
        unsigned long long c6 = b | (b << 2);
        unsigned long long hm = (c6 | (v << 6)) & ((1ull << HH) - 1ull);
        g_bits[(size_t)(base_plane + pl) * HH + h] = hm;
        cnt += (unsigned long long)__popcll(hm);
    }

    // Block reduction of cnt.
    #pragma unroll
    for (int o = 16; o > 0; o >>= 1)
        cnt += __shfl_down_sync(0xffffffffu, cnt, o);
    if ((t & 31) == 0) wsum[t >> 5] = cnt;
    __syncthreads();

    if (t == 0) {
        unsigned long long tot = 0ull;
        #pragma unroll
        for (int w = 0; w < 8; w++) tot += wsum[w];
        atomicAdd(&g_count, tot);
        __threadfence();
        unsigned old = atomicAdd(&g_arrive, 1u);
        if (old == MASK_GRID - 1u) {
            // Last CTA: all g_count adds are visible (fence-before-arrive).
            unsigned long long total = atomicAdd(&g_count, 0ull);
            double n = (double)NTOT;
            g_scale = (float)(n / (n - (double)total));
            // Reset for the next graph replay.
            atomicExch(&g_count, 0ull);
            atomicExch(&g_arrive, 0u);
        }
    }
}

// 8 floats (2 float4) per thread; 56 % 8 == 0 so one g_bits row covers all 8.
// Grid covers NTOT exactly (51,380,224 / 8 / 256 = 25088) — no bounds check.
__global__ __launch_bounds__(256) void apply_kernel(
    const float* __restrict__ x, float* __restrict__ out) {
    const int i = blockIdx.x * 256 + threadIdx.x;
    const int e = i << 3;                 // element index, fits in int
    const int r = e / WW;
    const int c = e - r * WW;             // in {0,8,...,48}

    const unsigned long long bits = __ldg(&g_bits[r]) >> c;
    const float s = g_scale;

    const float4* xp = reinterpret_cast<const float4*>(x) + 2 * i;
    float4 a = __ldcs(xp);
    float4 b = __ldcs(xp + 1);

    a.x = (bits & 1ull)         ? 0.0f : a.x * s;
    a.y = ((bits >> 1) & 1ull)  ? 0.0f : a.y * s;
    a.z = ((bits >> 2) & 1ull)  ? 0.0f : a.z * s;
    a.w = ((bits >> 3) & 1ull)  ? 0.0f : a.w * s;
    b.x = ((bits >> 4) & 1ull)  ? 0.0f : b.x * s;
    b.y = ((bits >> 5) & 1ull)  ? 0.0f : b.y * s;
    b.z = ((bits >> 6) & 1ull)  ? 0.0f : b.z * s;
    b.w = ((bits >> 7) & 1ull)  ? 0.0f : b.w * s;

    float4* op = reinterpret_cast<float4*>(out) + 2 * i;
    __stcs(op, a);
    __stcs(op + 1, b);
}

extern "C" void kernel_launch(void* const* d_in, const int* in_sizes, int n_in,
                              void* d_out, int out_size) {
    const float* x  = (const float*)d_in[0];
    const float* mu = (const float*)d_in[1];
    if (in_sizes[0] == NMASK) {           // defensive: swap if order differs
        x  = (const float*)d_in[1];
        mu = (const float*)d_in[0];
    }
    float* out = (float*)d_out;

    // gamma = DROP_PROB / bs^2 * feat^2 / (feat - bs + 1)^2 as float32.
    const double gamma_d = 0.1 / 49.0 * (56.0 * 56.0) / (50.0 * 50.0);
    const float gamma = (float)gamma_d;

    mask_kernel<<<MASK_GRID, 256>>>(mu, gamma);
    const int nblk = (int)(NTOT / 8 / 256);          // 25088 exact
    apply_kernel<<<nblk, 256>>>(x, out);
}